// round 15
// baseline (speedup 1.0000x reference)
#include <cuda_runtime.h>
#include <cuda_bf16.h>
#include <cstdint>

// ---------------- problem constants ----------------
#define BASE_VOCAB 32000
#define SVG_VOCAB  40000
#define TOTAL_VOCAB 72000
#define EMBED 2048
#define NTOK  2048

#define LM_PAD  72192   // 282 * 256
#define SVG_PAD 40192   // 157 * 256
#define HID_ROWS (NTOK + 128)   // pad: svg segment tiles may read past 2048

#define FP8_SCALE    64.0f      // applied to both operands pre-quantization
#define OUT_SCALE    (1.0f / (FP8_SCALE * FP8_SCALE))

// ---------------- scratch (e4m3) ----------------
__device__ uint8_t g_hidden[(size_t)HID_ROWS * EMBED];
__device__ uint8_t g_lmT[(size_t)LM_PAD * EMBED];
__device__ uint8_t g_svgT[(size_t)SVG_PAD * EMBED];
__device__ int g_perm[NTOK];
__device__ int g_counts[2];

// ---------------- helpers ----------------
__device__ __forceinline__ uint32_t smem_u32(const void* p) {
    uint32_t a;
    asm("{ .reg .u64 t; cvta.to.shared.u64 t, %1; cvt.u32.u64 %0, t; }" : "=r"(a) : "l"(p));
    return a;
}
// pack two floats -> two e4m3 bytes (hi<<8 | lo)
__device__ __forceinline__ uint16_t f2e4m3x2(float hi, float lo) {
    uint16_t v;
    asm("cvt.rn.satfinite.e4m3x2.f32 %0, %1, %2;" : "=h"(v) : "f"(hi), "f"(lo));
    return v;
}
__device__ __forceinline__ uint32_t pack4_e4m3(float a, float b, float c, float d) {
    uint32_t lo = f2e4m3x2(b, a);
    uint32_t hi = f2e4m3x2(d, c);
    return lo | (hi << 16);
}
__device__ __forceinline__ void cp16(uint32_t dst, const void* src) {
    asm volatile("{ .reg .u64 g; cvta.to.global.u64 g, %1; "
                 "cp.async.cg.shared.global [%0], [g], 16; }"
                 :: "r"(dst), "l"(src) : "memory");
}
#define CP_COMMIT()  asm volatile("cp.async.commit_group;" ::: "memory")
#define CP_WAIT(n)   asm volatile("cp.async.wait_group %0;" :: "n"(n) : "memory")

__device__ __forceinline__ void ldsm4(uint32_t* r, uint32_t addr) {
    asm volatile("ldmatrix.sync.aligned.m8n8.x4.shared.b16 {%0,%1,%2,%3}, [%4];"
                 : "=r"(r[0]), "=r"(r[1]), "=r"(r[2]), "=r"(r[3]) : "r"(addr));
}

__device__ __forceinline__ void mma_fp8(float* c, const uint32_t* a, const uint32_t* b) {
    asm volatile(
        "mma.sync.aligned.m16n8k32.row.col.f32.e4m3.e4m3.f32 "
        "{%0,%1,%2,%3}, {%4,%5,%6,%7}, {%8,%9}, {%0,%1,%2,%3};"
        : "+f"(c[0]), "+f"(c[1]), "+f"(c[2]), "+f"(c[3])
        : "r"(a[0]), "r"(a[1]), "r"(a[2]), "r"(a[3]), "r"(b[0]), "r"(b[1]));
}

// ---------------- partition ----------------
__global__ void partition_kernel(const int* __restrict__ ids, const int* __restrict__ sflags) {
    __shared__ int cnt0, s0, s1;
    if (threadIdx.x == 0) { cnt0 = 0; s0 = 0; s1 = 0; }
    __syncthreads();
    for (int t = threadIdx.x; t < NTOK; t += blockDim.x) {
        int id = ids[t];
        bool svg = (sflags[t] == 1) && (id >= BASE_VOCAB) && (id < TOTAL_VOCAB);
        if (!svg) atomicAdd(&cnt0, 1);
    }
    __syncthreads();
    int C0 = cnt0;
    for (int t = threadIdx.x; t < NTOK; t += blockDim.x) {
        int id = ids[t];
        bool svg = (sflags[t] == 1) && (id >= BASE_VOCAB) && (id < TOTAL_VOCAB);
        int slot = svg ? (C0 + atomicAdd(&s1, 1)) : atomicAdd(&s0, 1);
        g_perm[slot] = t;
    }
    __syncthreads();
    if (threadIdx.x == 0) { g_counts[0] = C0; g_counts[1] = NTOK - C0; }
}

// ---------------- merged prep: both transposes + gather ----------------
#define LM_XT     (TOTAL_VOCAB / 32)   // 2250
#define SVG_XT    (SVG_VOCAB / 32)     // 1250
#define GATHER_XT (NTOK / 16)          // 128
#define PREP_XT   (LM_XT + SVG_XT + GATHER_XT)

__global__ void __launch_bounds__(256)
prep_kernel(const int* __restrict__ ids, const int* __restrict__ sflags,
            const float* __restrict__ base_embed, const float* __restrict__ svg_embed,
            const float* __restrict__ lm_head, const float* __restrict__ svg_proj) {
    int bx = blockIdx.x, by = blockIdx.y;
    int tid = threadIdx.x;

    if (bx >= LM_XT + SVG_XT) {
        // ---- gather one token row into g_hidden (fp8, scaled) ----
        int s = (bx - LM_XT - SVG_XT) * 16 + by;
        int t = g_perm[s];
        int id = ids[t];
        bool svg = (sflags[t] == 1) && (id >= BASE_VOCAB) && (id < TOTAL_VOCAB);
        const float4* src = (const float4*)(svg ? (svg_embed + (size_t)(id - BASE_VOCAB) * EMBED)
                                                : (base_embed + (size_t)id * EMBED));
        uint32_t* dst = (uint32_t*)(g_hidden + (size_t)s * EMBED);
#pragma unroll
        for (int j = 0; j < 2; j++) {
            int i = tid + j * 256;          // 0..511
            float4 v = src[i];
            dst[i] = pack4_e4m3(v.x * FP8_SCALE, v.y * FP8_SCALE,
                                v.z * FP8_SCALE, v.w * FP8_SCALE);
        }
        return;
    }

    // ---- transpose tile K=128 x V=32, fp32 -> fp8 K-major ----
    const float* src;
    uint8_t* dst;
    int V, xt;
    if (bx < LM_XT) { src = lm_head; dst = g_lmT; V = TOTAL_VOCAB; xt = bx; }
    else            { src = svg_proj; dst = g_svgT; V = SVG_VOCAB; xt = bx - LM_XT; }

    __shared__ float tile[128][33];
    int v0 = xt * 32, k0 = by * 128;
#pragma unroll
    for (int j = 0; j < 16; j++) {
        int idx = tid + j * 256;           // 0..4095
        int kk = idx >> 5, vv = idx & 31;
        tile[kk][vv] = src[(size_t)(k0 + kk) * V + v0 + vv];
    }
    __syncthreads();
    uint32_t* du = (uint32_t*)dst;
#pragma unroll
    for (int j = 0; j < 4; j++) {
        int idx = tid + j * 256;           // 0..1023
        int vv = idx >> 5, kq = idx & 31;
        uint32_t val = pack4_e4m3(tile[kq * 4 + 0][vv] * FP8_SCALE,
                                  tile[kq * 4 + 1][vv] * FP8_SCALE,
                                  tile[kq * 4 + 2][vv] * FP8_SCALE,
                                  tile[kq * 4 + 3][vv] * FP8_SCALE);
        du[(size_t)(v0 + vv) * (EMBED / 4) + (k0 >> 2) + kq] = val;
    }
}

// ---------------- fp8 GEMM (128x256 tile, 512 thr) + fused fillneg ----------------
// blockIdx.y: [0, LM_NB) lm | [LM_NB, +SVG_NB) svg | tail FILL_NB fill tiles.
// 16 warps: wm = wid>>2 (4 along M, 32 rows), wn = wid&3 (4 along N, 64 cols).
// 2-stage cp.async double buffer; smem 110.6 KB; occ=1 (4 warps/SMSP preserved).
#define KT   128
#define MT   128
#define NT   256
#define NTHR 512
#define KCH  (EMBED / KT)       // 16
#define ROWU 36
#define ROWB (ROWU * 4)         // 144 bytes
#define ABU  (MT * ROWU)        // 4608
#define BBU  (NT * ROWU)        // 9216
#define STU  (ABU + BBU)        // one stage: 13824 u32
#define SMEM_BYTES (2 * STU * 4)   // 110592

#define LM_NB   ((TOTAL_VOCAB + NT - 1) / NT)   // 282
#define SVG_NB  ((SVG_VOCAB + NT - 1) / NT)     // 157
#define FILL_NB (BASE_VOCAB / NT)               // 125
#define GEMM_NB (LM_NB + SVG_NB)

__global__ void __launch_bounds__(NTHR, 1)
gemm_kernel(const uint8_t* __restrict__ lmT, const uint8_t* __restrict__ svgT,
            float* __restrict__ out) {
    int nb = blockIdx.y;
    int mt = blockIdx.x;

    if (nb >= GEMM_NB) {
        // ---- fill tile: -1e30 into base-vocab cols of svg rows (128 rows x 256 cols) ----
        int fb = nb - GEMM_NB;              // 0..124
        int count1 = g_counts[1];
        if (mt * MT >= count1) return;
        int C0 = g_counts[0];
        int col0 = fb * NT;
        float4 v = make_float4(-1e30f, -1e30f, -1e30f, -1e30f);
        int tid = threadIdx.x;
#pragma unroll
        for (int j = 0; j < 16; j++) {
            int idx = tid + j * NTHR;       // 0..8191
            int row = idx >> 6, c4 = idx & 63;
            int grow = mt * MT + row;
            if (grow < count1) {
                int token = g_perm[C0 + grow];
                *(float4*)(out + (size_t)token * TOTAL_VOCAB + col0 + c4 * 4) = v;
            }
        }
        return;
    }

    int sel, Ncols, colOff;
    const uint8_t* Bmat;
    if (nb < LM_NB) { sel = 0; Bmat = lmT; Ncols = TOTAL_VOCAB; colOff = 0; }
    else            { sel = 1; Bmat = svgT; Ncols = SVG_VOCAB; colOff = BASE_VOCAB; nb -= LM_NB; }

    int count = g_counts[sel];
    if (mt * MT >= count) return;
    int segBase = sel ? g_counts[0] : 0;

    extern __shared__ uint32_t sm[];
    uint32_t sm_b = smem_u32(sm);
    int tid = threadIdx.x;
    int wid = tid >> 5, lane = tid & 31;
    int g = lane >> 2, t = lane & 3;
    int wm = wid >> 2, wn = wid & 3;

    // ldmatrix per-lane source rows/bytes (m8n8.x4 canonical distribution)
    int l7  = lane & 7, sel8 = lane >> 3;
    int arow  = l7 + (sel8 & 1) * 8;
    int abyte = (sel8 >> 1) * 16;
    int brow  = l7 + (sel8 >> 1) * 8;
    int bbyte = (sel8 & 1) * 16;

    const uint8_t* Aptr = g_hidden + (size_t)(segBase + mt * MT) * EMBED;
    const uint8_t* Bptr = Bmat + (size_t)(nb * NT) * EMBED;

    auto load_chunk = [&](int k, int buf) {
        int k0 = k * KT;
        uint32_t sA = sm_b + buf * STU * 4;
        uint32_t sB = sA + ABU * 4;
        // A: 128 rows x 8 cp16 = 1024; B: 256 rows x 8 = 2048; 512 threads
#pragma unroll
        for (int j = 0; j < 2; j++) {
            int i = tid + j * NTHR;
            int r = i >> 3, q = i & 7;
            cp16(sA + r * ROWB + q * 16, Aptr + (size_t)r * EMBED + k0 + q * 16);
        }
#pragma unroll
        for (int j = 0; j < 4; j++) {
            int i = tid + j * NTHR;
            int r = i >> 3, q = i & 7;
            cp16(sB + r * ROWB + q * 16, Bptr + (size_t)r * EMBED + k0 + q * 16);
        }
        CP_COMMIT();
    };

    float acc[2][8][4];
#pragma unroll
    for (int mf = 0; mf < 2; mf++)
#pragma unroll
        for (int nf = 0; nf < 8; nf++)
#pragma unroll
            for (int i = 0; i < 4; i++) acc[mf][nf][i] = 0.f;

    load_chunk(0, 0);

#pragma unroll 1
    for (int k = 0; k < KCH; k++) {
        int buf = k & 1;
        if (k + 1 < KCH) { load_chunk(k + 1, (k + 1) & 1); CP_WAIT(1); }
        else             { CP_WAIT(0); }
        __syncthreads();

        uint32_t sA = sm_b + buf * STU * 4;
        uint32_t sB = sA + ABU * 4;
        uint32_t aAddr0 = sA + (uint32_t)(wm * 32 + arow) * ROWB + abyte;
        uint32_t aAddr1 = aAddr0 + 16 * ROWB;
        uint32_t bAddr  = sB + (uint32_t)(wn * 64 + brow) * ROWB + bbyte;

#pragma unroll
        for (int ks = 0; ks < 4; ks++) {
            uint32_t koff = ks * 32;
            uint32_t a[2][4];
            ldsm4(a[0], aAddr0 + koff);
            ldsm4(a[1], aAddr1 + koff);
            uint32_t b[8][2];
#pragma unroll
            for (int p = 0; p < 4; p++)
                ldsm4(&b[2 * p][0], bAddr + (uint32_t)(p * 16) * ROWB + koff);
#pragma unroll
            for (int mf = 0; mf < 2; mf++)
#pragma unroll
                for (int nf = 0; nf < 8; nf++)
                    mma_fp8(acc[mf][nf], a[mf], b[nf]);
        }
        __syncthreads();
    }

    // epilogue: scatter rows through the token permutation, undo fp8 scaling
#pragma unroll
    for (int mf = 0; mf < 2; mf++) {
#pragma unroll
        for (int sub = 0; sub < 2; sub++) {
            int rloc = wm * 32 + mf * 16 + g + sub * 8;
            int grow = mt * MT + rloc;
            if (grow >= count) continue;
            int token = g_perm[segBase + grow];
            float* orow = out + (size_t)token * TOTAL_VOCAB + colOff
                        + (size_t)nb * NT + wn * 64;
#pragma unroll
            for (int nf = 0; nf < 8; nf++) {
                int c = nb * NT + wn * 64 + nf * 8 + 2 * t;
                if (c < Ncols) {
                    float2 v = make_float2(acc[mf][nf][2 * sub] * OUT_SCALE,
                                           acc[mf][nf][2 * sub + 1] * OUT_SCALE);
                    *(float2*)(orow + nf * 8 + 2 * t) = v;
                }
            }
        }
    }
}

// ---------------- launch ----------------
extern "C" void kernel_launch(void* const* d_in, const int* in_sizes, int n_in,
                              void* d_out, int out_size) {
    const int*   input_ids  = (const int*)d_in[0];
    const int*   svg_flags  = (const int*)d_in[1];
    const float* base_embed = (const float*)d_in[2];
    const float* svg_embed  = (const float*)d_in[3];
    const float* lm_head    = (const float*)d_in[4];
    const float* svg_proj   = (const float*)d_in[5];
    float* out = (float*)d_out;

    cudaFuncSetAttribute(gemm_kernel, cudaFuncAttributeMaxDynamicSharedMemorySize, SMEM_BYTES);

    uint8_t* lmT;  cudaGetSymbolAddress((void**)&lmT,  g_lmT);
    uint8_t* svgT; cudaGetSymbolAddress((void**)&svgT, g_svgT);

    partition_kernel<<<1, 256>>>(input_ids, svg_flags);
    prep_kernel<<<dim3(PREP_XT, 16), 256>>>(input_ids, svg_flags,
                                            base_embed, svg_embed, lm_head, svg_proj);
    gemm_kernel<<<dim3(16, GEMM_NB + FILL_NB), NTHR, SMEM_BYTES>>>(lmT, svgT, out);
}

// round 16
// speedup vs baseline: 1.1558x; 1.1558x over previous
#include <cuda_runtime.h>
#include <cuda_bf16.h>
#include <cstdint>

// ---------------- problem constants ----------------
#define BASE_VOCAB 32000
#define SVG_VOCAB  40000
#define TOTAL_VOCAB 72000
#define EMBED 2048
#define NTOK  2048

#define LM_PAD  72192
#define SVG_PAD 40192
#define HID_ROWS (NTOK + 128)   // pad: svg segment tiles may read past 2048

#define FP8_SCALE    64.0f      // applied to both operands pre-quantization
#define OUT_SCALE    (1.0f / (FP8_SCALE * FP8_SCALE))

// ---------------- scratch (e4m3) ----------------
__device__ uint8_t g_hidden[(size_t)HID_ROWS * EMBED];
__device__ uint8_t g_lmT[(size_t)LM_PAD * EMBED];
__device__ uint8_t g_svgT[(size_t)SVG_PAD * EMBED];
__device__ int g_perm[NTOK];
__device__ int g_counts[2];

// ---------------- helpers ----------------
__device__ __forceinline__ uint32_t smem_u32(const void* p) {
    uint32_t a;
    asm("{ .reg .u64 t; cvta.to.shared.u64 t, %1; cvt.u32.u64 %0, t; }" : "=r"(a) : "l"(p));
    return a;
}
// pack two floats -> two e4m3 bytes (hi<<8 | lo)
__device__ __forceinline__ uint16_t f2e4m3x2(float hi, float lo) {
    uint16_t v;
    asm("cvt.rn.satfinite.e4m3x2.f32 %0, %1, %2;" : "=h"(v) : "f"(hi), "f"(lo));
    return v;
}
__device__ __forceinline__ uint32_t pack4_e4m3(float a, float b, float c, float d) {
    uint32_t lo = f2e4m3x2(b, a);
    uint32_t hi = f2e4m3x2(d, c);
    return lo | (hi << 16);
}
__device__ __forceinline__ void cp16(uint32_t dst, const void* src) {
    asm volatile("{ .reg .u64 g; cvta.to.global.u64 g, %1; "
                 "cp.async.cg.shared.global [%0], [g], 16; }"
                 :: "r"(dst), "l"(src) : "memory");
}
#define CP_COMMIT()  asm volatile("cp.async.commit_group;" ::: "memory")
#define CP_WAIT(n)   asm volatile("cp.async.wait_group %0;" :: "n"(n) : "memory")

__device__ __forceinline__ void ldsm4(uint32_t* r, uint32_t addr) {
    asm volatile("ldmatrix.sync.aligned.m8n8.x4.shared.b16 {%0,%1,%2,%3}, [%4];"
                 : "=r"(r[0]), "=r"(r[1]), "=r"(r[2]), "=r"(r[3]) : "r"(addr));
}

__device__ __forceinline__ void mma_fp8(float* c, const uint32_t* a, const uint32_t* b) {
    asm volatile(
        "mma.sync.aligned.m16n8k32.row.col.f32.e4m3.e4m3.f32 "
        "{%0,%1,%2,%3}, {%4,%5,%6,%7}, {%8,%9}, {%0,%1,%2,%3};"
        : "+f"(c[0]), "+f"(c[1]), "+f"(c[2]), "+f"(c[3])
        : "r"(a[0]), "r"(a[1]), "r"(a[2]), "r"(a[3]), "r"(b[0]), "r"(b[1]));
}

// ---------------- partition ----------------
__global__ void partition_kernel(const int* __restrict__ ids, const int* __restrict__ sflags) {
    __shared__ int cnt0, s0, s1;
    if (threadIdx.x == 0) { cnt0 = 0; s0 = 0; s1 = 0; }
    __syncthreads();
    for (int t = threadIdx.x; t < NTOK; t += blockDim.x) {
        int id = ids[t];
        bool svg = (sflags[t] == 1) && (id >= BASE_VOCAB) && (id < TOTAL_VOCAB);
        if (!svg) atomicAdd(&cnt0, 1);
    }
    __syncthreads();
    int C0 = cnt0;
    for (int t = threadIdx.x; t < NTOK; t += blockDim.x) {
        int id = ids[t];
        bool svg = (sflags[t] == 1) && (id >= BASE_VOCAB) && (id < TOTAL_VOCAB);
        int slot = svg ? (C0 + atomicAdd(&s1, 1)) : atomicAdd(&s0, 1);
        g_perm[slot] = t;
    }
    __syncthreads();
    if (threadIdx.x == 0) { g_counts[0] = C0; g_counts[1] = NTOK - C0; }
}

// ---------------- merged prep: both transposes + gather ----------------
#define LM_XT     (TOTAL_VOCAB / 32)   // 2250
#define SVG_XT    (SVG_VOCAB / 32)     // 1250
#define GATHER_XT (NTOK / 16)          // 128
#define PREP_XT   (LM_XT + SVG_XT + GATHER_XT)

__global__ void __launch_bounds__(256)
prep_kernel(const int* __restrict__ ids, const int* __restrict__ sflags,
            const float* __restrict__ base_embed, const float* __restrict__ svg_embed,
            const float* __restrict__ lm_head, const float* __restrict__ svg_proj) {
    int bx = blockIdx.x, by = blockIdx.y;
    int tid = threadIdx.x;

    if (bx >= LM_XT + SVG_XT) {
        // ---- gather one token row into g_hidden (fp8, scaled) ----
        int s = (bx - LM_XT - SVG_XT) * 16 + by;
        int t = g_perm[s];
        int id = ids[t];
        bool svg = (sflags[t] == 1) && (id >= BASE_VOCAB) && (id < TOTAL_VOCAB);
        const float4* src = (const float4*)(svg ? (svg_embed + (size_t)(id - BASE_VOCAB) * EMBED)
                                                : (base_embed + (size_t)id * EMBED));
        uint32_t* dst = (uint32_t*)(g_hidden + (size_t)s * EMBED);
#pragma unroll
        for (int j = 0; j < 2; j++) {
            int i = tid + j * 256;          // 0..511
            float4 v = src[i];
            dst[i] = pack4_e4m3(v.x * FP8_SCALE, v.y * FP8_SCALE,
                                v.z * FP8_SCALE, v.w * FP8_SCALE);
        }
        return;
    }

    // ---- transpose tile K=128 x V=32, fp32 -> fp8 K-major (float4 global reads) ----
    const float* src;
    uint8_t* dst;
    int V, xt;
    if (bx < LM_XT) { src = lm_head; dst = g_lmT; V = TOTAL_VOCAB; xt = bx; }
    else            { src = svg_proj; dst = g_svgT; V = SVG_VOCAB; xt = bx - LM_XT; }

    __shared__ float tile[128][33];
    int v0 = xt * 32, k0 = by * 128;
#pragma unroll
    for (int j = 0; j < 4; j++) {
        int idx = tid + j * 256;           // 0..1023
        int kk = idx >> 3, vq = idx & 7;   // kk: 0..127, vq: float4 index 0..7
        float4 v = *(const float4*)&src[(size_t)(k0 + kk) * V + v0 + vq * 4];
        tile[kk][vq * 4 + 0] = v.x;
        tile[kk][vq * 4 + 1] = v.y;
        tile[kk][vq * 4 + 2] = v.z;
        tile[kk][vq * 4 + 3] = v.w;
    }
    __syncthreads();
    uint32_t* du = (uint32_t*)dst;
#pragma unroll
    for (int j = 0; j < 4; j++) {
        int idx = tid + j * 256;           // 0..1023
        int vv = idx >> 5, kq = idx & 31;  // kq: u32 index within 128-K tile
        uint32_t val = pack4_e4m3(tile[kq * 4 + 0][vv] * FP8_SCALE,
                                  tile[kq * 4 + 1][vv] * FP8_SCALE,
                                  tile[kq * 4 + 2][vv] * FP8_SCALE,
                                  tile[kq * 4 + 3][vv] * FP8_SCALE);
        du[(size_t)(v0 + vv) * (EMBED / 4) + (k0 >> 2) + kq] = val;
    }
}

// ---------------- fp8 GEMM + fused fillneg, merged segments ----------------
// blockIdx.y: [0, LM_NB) lm | [LM_NB, +SVG_NB) svg | tail FILL_NB fill tiles.
// GEMM: CTA tile 128x128, K chunk 128, 3-stage cp.async ring, 1 sync/chunk, occ=2.
#define KT   128
#define MT   128
#define NT   128
#define KCH  (EMBED / KT)       // 16
#define ROWU 36
#define ROWB (ROWU * 4)         // 144 bytes
#define ABU  (MT * ROWU)
#define STU  (2 * ABU)
#define STAGES 3
#define SMEM_BYTES (STAGES * STU * 4)   // 110592

#define LM_NB   ((TOTAL_VOCAB + NT - 1) / NT)   // 563
#define SVG_NB  ((SVG_VOCAB + NT - 1) / NT)     // 313
#define FILL_NB (BASE_VOCAB / NT)               // 250
#define GEMM_NB (LM_NB + SVG_NB)

__global__ void __launch_bounds__(256, 2)
gemm_kernel(const uint8_t* __restrict__ lmT, const uint8_t* __restrict__ svgT,
            float* __restrict__ out) {
    int nb = blockIdx.y;
    int mt = blockIdx.x;

    if (nb >= GEMM_NB) {
        // ---- fill tile: -1e30 into base-vocab cols of svg rows ----
        int fb = nb - GEMM_NB;              // 0..249
        int count1 = g_counts[1];
        if (mt * MT >= count1) return;
        int C0 = g_counts[0];
        int col0 = fb * NT;
        float4 v = make_float4(-1e30f, -1e30f, -1e30f, -1e30f);
        int tid = threadIdx.x;
#pragma unroll
        for (int j = 0; j < 16; j++) {
            int idx = tid + j * 256;        // 0..4095
            int row = idx >> 5, c4 = idx & 31;
            int grow = mt * MT + row;
            if (grow < count1) {
                int token = g_perm[C0 + grow];
                *(float4*)(out + (size_t)token * TOTAL_VOCAB + col0 + c4 * 4) = v;
            }
        }
        return;
    }

    int sel, Ncols, colOff;
    const uint8_t* Bmat;
    if (nb < LM_NB) { sel = 0; Bmat = lmT; Ncols = TOTAL_VOCAB; colOff = 0; }
    else            { sel = 1; Bmat = svgT; Ncols = SVG_VOCAB; colOff = BASE_VOCAB; nb -= LM_NB; }

    int count = g_counts[sel];
    if (mt * MT >= count) return;
    int segBase = sel ? g_counts[0] : 0;

    extern __shared__ uint32_t sm[];
    uint32_t sm_b = smem_u32(sm);
    int tid = threadIdx.x;
    int wid = tid >> 5, lane = tid & 31;
    int g = lane >> 2, t = lane & 3;
    int wm = wid >> 1, wn = wid & 1;

    // ldmatrix per-lane source rows/bytes (m8n8.x4 canonical distribution)
    int l7  = lane & 7, sel8 = lane >> 3;
    int arow  = l7 + (sel8 & 1) * 8;
    int abyte = (sel8 >> 1) * 16;
    int brow  = l7 + (sel8 >> 1) * 8;
    int bbyte = (sel8 & 1) * 16;

    const uint8_t* Aptr = g_hidden + (size_t)(segBase + mt * MT) * EMBED;
    const uint8_t* Bptr = Bmat + (size_t)(nb * NT) * EMBED;

    auto load_chunk = [&](int k, int stg) {
        int k0 = k * KT;
        uint32_t sA = sm_b + stg * STU * 4;
        uint32_t sB = sA + ABU * 4;
#pragma unroll
        for (int j = 0; j < 4; j++) {
            int i = tid + j * 256;
            int r = i >> 3, q = i & 7;
            cp16(sA + r * ROWB + q * 16, Aptr + (size_t)r * EMBED + k0 + q * 16);
        }
#pragma unroll
        for (int j = 0; j < 4; j++) {
            int i = tid + j * 256;
            int r = i >> 3, q = i & 7;
            cp16(sB + r * ROWB + q * 16, Bptr + (size_t)r * EMBED + k0 + q * 16);
        }
        CP_COMMIT();
    };

    float acc[2][8][4];
#pragma unroll
    for (int mf = 0; mf < 2; mf++)
#pragma unroll
        for (int nf = 0; nf < 8; nf++)
#pragma unroll
            for (int i = 0; i < 4; i++) acc[mf][nf][i] = 0.f;

    load_chunk(0, 0);
    load_chunk(1, 1);

    int stg = 0;
#pragma unroll 1
    for (int k = 0; k < KCH; k++) {
        if (k < KCH - 1) { CP_WAIT(1); }
        else             { CP_WAIT(0); }
        __syncthreads();

        if (k + 2 < KCH) {
            int ns = stg + 2; if (ns >= STAGES) ns -= STAGES;
            load_chunk(k + 2, ns);
        }

        uint32_t sA = sm_b + stg * STU * 4;
        uint32_t sB = sA + ABU * 4;
        uint32_t aAddr0 = sA + (uint32_t)(wm * 32 + arow) * ROWB + abyte;
        uint32_t aAddr1 = aAddr0 + 16 * ROWB;
        uint32_t bAddr  = sB + (uint32_t)(wn * 64 + brow) * ROWB + bbyte;

#pragma unroll
        for (int ks = 0; ks < 4; ks++) {
            uint32_t koff = ks * 32;
            uint32_t a[2][4];
            ldsm4(a[0], aAddr0 + koff);
            ldsm4(a[1], aAddr1 + koff);
            uint32_t b[8][2];
#pragma unroll
            for (int p = 0; p < 4; p++)
                ldsm4(&b[2 * p][0], bAddr + (uint32_t)(p * 16) * ROWB + koff);
#pragma unroll
            for (int mf = 0; mf < 2; mf++)
#pragma unroll
                for (int nf = 0; nf < 8; nf++)
                    mma_fp8(acc[mf][nf], a[mf], b[nf]);
        }

        if (++stg >= STAGES) stg = 0;
    }

    // epilogue: scatter rows through the token permutation, undo fp8 scaling
#pragma unroll
    for (int mf = 0; mf < 2; mf++) {
#pragma unroll
        for (int sub = 0; sub < 2; sub++) {
            int rloc = wm * 32 + mf * 16 + g + sub * 8;
            int grow = mt * MT + rloc;
            if (grow >= count) continue;
            int token = g_perm[segBase + grow];
            float* orow = out + (size_t)token * TOTAL_VOCAB + colOff
                        + (size_t)nb * NT + wn * 64;
#pragma unroll
            for (int nf = 0; nf < 8; nf++) {
                int c = nb * NT + wn * 64 + nf * 8 + 2 * t;
                if (c < Ncols) {
                    float2 v = make_float2(acc[mf][nf][2 * sub] * OUT_SCALE,
                                           acc[mf][nf][2 * sub + 1] * OUT_SCALE);
                    *(float2*)(orow + nf * 8 + 2 * t) = v;
                }
            }
        }
    }
}

// ---------------- launch ----------------
extern "C" void kernel_launch(void* const* d_in, const int* in_sizes, int n_in,
                              void* d_out, int out_size) {
    const int*   input_ids  = (const int*)d_in[0];
    const int*   svg_flags  = (const int*)d_in[1];
    const float* base_embed = (const float*)d_in[2];
    const float* svg_embed  = (const float*)d_in[3];
    const float* lm_head    = (const float*)d_in[4];
    const float* svg_proj   = (const float*)d_in[5];
    float* out = (float*)d_out;

    cudaFuncSetAttribute(gemm_kernel, cudaFuncAttributeMaxDynamicSharedMemorySize, SMEM_BYTES);

    uint8_t* lmT;  cudaGetSymbolAddress((void**)&lmT,  g_lmT);
    uint8_t* svgT; cudaGetSymbolAddress((void**)&svgT, g_svgT);

    partition_kernel<<<1, 1024>>>(input_ids, svg_flags);
    prep_kernel<<<dim3(PREP_XT, 16), 256>>>(input_ids, svg_flags,
                                            base_embed, svg_embed, lm_head, svg_proj);
    gemm_kernel<<<dim3(16, GEMM_NB + FILL_NB), 256, SMEM_BYTES>>>(lmT, svgT, out);
}